// round 16
// baseline (speedup 1.0000x reference)
#include <cuda_runtime.h>
#include <cuda_bf16.h>
#include <math.h>
#include <stdint.h>

// Problem dims
#define BQ 16
#define CQ 512
#define NQ 4096   // H*W
#define KQ 64
#define SPLITK 2

// Scratch (allocation-free rule: device globals)
__device__ __align__(128) float         g_part[SPLITK][BQ * KQ * NQ]; // split-k partials
__device__ __align__(128) float         g_attn[BQ * KQ * NQ]; // attn probs (softmaxed)
__device__ __align__(128) float         g_rs  [BQ * NQ];      // 1/(1e-9+colsum)
__device__ __align__(128) __nv_bfloat16 g_y2h [BQ * CQ * NQ]; // ranked y2, bf16 [b][c][n]
__device__ __align__(128) __nv_bfloat16 g_w2h [CQ * CQ];      // conv2 weight [c][o] bf16
__device__ __align__(128) float         g_l1T [KQ * CQ];      // lin1 weight [k][c] fp32
__device__ __align__(128) float         g_w01T[CQ * KQ];      // fused (L0@W1)^T [c][k]
__device__ __align__(128) float         g_b01 [KQ];           // fused bias L0@b1

// ---------------------------------------------------------------------------
// helpers
// ---------------------------------------------------------------------------
__device__ __forceinline__ void cpa16(void* smem_dst, const void* gmem_src) {
    unsigned sa = (unsigned)__cvta_generic_to_shared(smem_dst);
    asm volatile("cp.async.ca.shared.global [%0], [%1], 16;" :: "r"(sa), "l"(gmem_src));
}
__device__ __forceinline__ void cpa16cg(void* smem_dst, const void* gmem_src) {
    unsigned sa = (unsigned)__cvta_generic_to_shared(smem_dst);
    asm volatile("cp.async.cg.shared.global [%0], [%1], 16;" :: "r"(sa), "l"(gmem_src));
}
__device__ __forceinline__ void cpa_commit() {
    asm volatile("cp.async.commit_group;" ::: "memory");
}
template<int N>
__device__ __forceinline__ void cpa_wait() {
    asm volatile("cp.async.wait_group %0;" :: "n"(N) : "memory");
}
__device__ __forceinline__ uint32_t smem_u32(const void* p) {
    return (uint32_t)__cvta_generic_to_shared(p);
}

// ---------------------------------------------------------------------------
// Transpose fp32: AT[k][m] = A[m][k]
// ---------------------------------------------------------------------------
__global__ __launch_bounds__(256) void transpose_kernel(
    const float* __restrict__ A, float* __restrict__ AT, int M, int K)
{
    __shared__ float t[32][33];
    const int m0 = blockIdx.y * 32, k0 = blockIdx.x * 32;
    const int x = threadIdx.x, y = threadIdx.y;
    #pragma unroll
    for (int yy = y; yy < 32; yy += 8)
        t[yy][x] = A[(size_t)(m0 + yy) * K + k0 + x];
    __syncthreads();
    #pragma unroll
    for (int yy = y; yy < 32; yy += 8)
        AT[(size_t)(k0 + yy) * M + m0 + x] = t[x][yy];
}

// Transpose + bf16 convert: AT[k][m] = bf16(A[m][k])
__global__ __launch_bounds__(256) void transpose_bf16_kernel(
    const float* __restrict__ A, __nv_bfloat16* __restrict__ AT, int M, int K)
{
    __shared__ float t[32][33];
    const int m0 = blockIdx.y * 32, k0 = blockIdx.x * 32;
    const int x = threadIdx.x, y = threadIdx.y;
    #pragma unroll
    for (int yy = y; yy < 32; yy += 8)
        t[yy][x] = A[(size_t)(m0 + yy) * K + k0 + x];
    __syncthreads();
    #pragma unroll
    for (int yy = y; yy < 32; yy += 8)
        AT[(size_t)(k0 + yy) * M + m0 + x] = __float2bfloat16_rn(t[x][yy]);
}

// ---------------------------------------------------------------------------
// Weight fusion: W01T[c][k] = sum_o W1[o][c] * L0[k][o], b01[k] = L0@b1
// ---------------------------------------------------------------------------
__global__ __launch_bounds__(256) void fuse_w01_kernel(
    const float* __restrict__ w1, const float* __restrict__ l0,
    const float* __restrict__ b1, float* __restrict__ w01T, float* __restrict__ b01)
{
    __shared__ float sw[16][17];
    __shared__ float sl[16][17];
    const int c0 = blockIdx.x * 16, k0 = blockIdx.y * 16;
    const int tx = threadIdx.x, ty = threadIdx.y;
    float acc = 0.f;
    for (int o0 = 0; o0 < CQ; o0 += 16) {
        sw[ty][tx] = w1[(size_t)(o0 + ty) * CQ + c0 + tx];
        sl[ty][tx] = l0[(size_t)(k0 + ty) * CQ + o0 + tx];
        __syncthreads();
        #pragma unroll
        for (int o = 0; o < 16; o++)
            acc += sw[o][tx] * sl[ty][o];
        __syncthreads();
    }
    w01T[(size_t)(c0 + tx) * KQ + k0 + ty] = acc;
    if (blockIdx.x == 0 && tx == 0) {
        const int k = k0 + ty;
        float s = 0.f;
        for (int o = 0; o < CQ; o++) s += l0[(size_t)k * CQ + o] * b1[o];
        b01[k] = s;
    }
}

// ---------------------------------------------------------------------------
// fp32 SGEMM-NT, split-K over gridDim.y: block y handles k-range
// [y*Kc, (y+1)*Kc) and writes its partial (+bias when y==0, EPI==1) to
// part + y*partStride. S-stage cp.async pipeline, tail-safe waits.
// ---------------------------------------------------------------------------
template<int M, int Kc, int Nn, int BM, int BN, int BK, int TM, int TN, int EPI, int S>
__global__ __launch_bounds__((BM/TM)*(BN/TN))
void gemm_nt_splitk_kernel(const float* __restrict__ AT,   // full K x M
                           const float* __restrict__ Bm,   // full K x Nn per batch
                           const float* __restrict__ bias,
                           float* __restrict__ part,       // [SPLITK][B][M][Nn]
                           int Kfull)
{
    constexpr int THREADS = (BM/TM)*(BN/TN);
    __shared__ float As[S][BK][BM];
    __shared__ float Bs[S][BK][BN];

    const int b    = blockIdx.z;
    const int half = blockIdx.y;
    const int koff = half * Kc;
    const int bm0  = 0;
    const int bn0  = blockIdx.x * BN;
    const float* Bp = Bm + (size_t)b * Kfull * Nn;
    float*       Op = part + (size_t)half * BQ * M * Nn + (size_t)b * M * Nn;

    const int tid = threadIdx.x;
    const int tx  = tid % (BN/TN);
    const int ty  = tid / (BN/TN);

    float acc[TM][TN];
    #pragma unroll
    for (int i = 0; i < TM; i++)
        #pragma unroll
        for (int j = 0; j < TN; j++) acc[i][j] = 0.f;

    auto load_tile = [&](int k0, int s) {
        #pragma unroll
        for (int i = tid; i < BK*BM/4; i += THREADS) {
            int k = (i*4) / BM, m = (i*4) % BM;
            cpa16(&As[s][k][m], &AT[(size_t)(koff + k0 + k) * M + bm0 + m]);
        }
        #pragma unroll
        for (int i = tid; i < BK*BN/4; i += THREADS) {
            int k = (i*4) / BN, n = (i*4) % BN;
            cpa16(&Bs[s][k][n], &Bp[(size_t)(koff + k0 + k) * Nn + bn0 + n]);
        }
        cpa_commit();
    };

    constexpr int NT = Kc / BK;
    #pragma unroll
    for (int p = 0; p < S - 1; p++) load_tile(p * BK, p);

    for (int t = 0; t < NT; t++) {
        if (t < NT - (S - 1)) cpa_wait<S - 2>();
        else                  cpa_wait<0>();
        __syncthreads();
        if (t + S - 1 < NT) load_tile((t + S - 1) * BK, (t + S - 1) % S);

        const int s = t % S;
        float a[2][TM], bb[2][TN];
        #pragma unroll
        for (int v = 0; v < TM; v += 4)
            *reinterpret_cast<float4*>(&a[0][v]) =
                *reinterpret_cast<const float4*>(&As[s][0][ty*TM + v]);
        #pragma unroll
        for (int v = 0; v < TN; v += 4)
            *reinterpret_cast<float4*>(&bb[0][v]) =
                *reinterpret_cast<const float4*>(&Bs[s][0][tx*TN + v]);

        #pragma unroll
        for (int k = 0; k < BK; k++) {
            if (k + 1 < BK) {
                #pragma unroll
                for (int v = 0; v < TM; v += 4)
                    *reinterpret_cast<float4*>(&a[(k+1)&1][v]) =
                        *reinterpret_cast<const float4*>(&As[s][k+1][ty*TM + v]);
                #pragma unroll
                for (int v = 0; v < TN; v += 4)
                    *reinterpret_cast<float4*>(&bb[(k+1)&1][v]) =
                        *reinterpret_cast<const float4*>(&Bs[s][k+1][tx*TN + v]);
            }
            const int c = k & 1;
            #pragma unroll
            for (int i = 0; i < TM; i++)
                #pragma unroll
                for (int j = 0; j < TN; j++)
                    acc[i][j] += a[c][i] * bb[c][j];
        }
    }

    #pragma unroll
    for (int i = 0; i < TM; i++) {
        const int m = bm0 + ty * TM + i;
        float bval = 0.f;
        if (EPI == 1 && half == 0) bval = bias[m];
        #pragma unroll
        for (int j = 0; j < TN; j += 4) {
            const int n = bn0 + tx * TN + j;
            float vv[4];
            #pragma unroll
            for (int u = 0; u < 4; u++) vv[u] = acc[i][j + u];
            if (EPI == 1 && half == 0) {
                #pragma unroll
                for (int u = 0; u < 4; u++) vv[u] += bval;
            }
            float4 o; o.x = vv[0]; o.y = vv[1]; o.z = vv[2]; o.w = vv[3];
            *reinterpret_cast<float4*>(&Op[(size_t)m * Nn + n]) = o;
        }
    }
}

// ---------------------------------------------------------------------------
// Softmax over token axis — sums the SPLITK partials (ascending half order =
// k-ascending reassociation), then softmax. Warp-shuffle reductions.
// ---------------------------------------------------------------------------
__global__ __launch_bounds__(256) void softmax_kernel(
    const float* __restrict__ part, float* __restrict__ attn)
{
    const int row = blockIdx.x;
    float* p = attn + (size_t)row * NQ;
    const int tid  = threadIdx.x;
    const int lane = tid & 31;
    const int wrp  = tid >> 5;
    __shared__ float red[8];
    const size_t stride = (size_t)BQ * KQ * NQ;

    float v[NQ / 256];
    float m = -INFINITY;
    #pragma unroll
    for (int i = 0; i < NQ / 256; i++) {
        const size_t off = (size_t)row * NQ + tid + i * 256;
        float s0 = part[off];
        #pragma unroll
        for (int h = 1; h < SPLITK; h++) s0 += part[off + h * stride];
        v[i] = s0;
        m = fmaxf(m, v[i]);
    }
    #pragma unroll
    for (int o = 16; o > 0; o >>= 1)
        m = fmaxf(m, __shfl_xor_sync(0xffffffffu, m, o));
    if (lane == 0) red[wrp] = m;
    __syncthreads();
    m = red[lane & 7];
    #pragma unroll
    for (int o = 4; o > 0; o >>= 1)
        m = fmaxf(m, __shfl_xor_sync(0xffffffffu, m, o));

    float s = 0.f;
    #pragma unroll
    for (int i = 0; i < NQ / 256; i++) {
        v[i] = expf(v[i] - m);
        s += v[i];
    }
    #pragma unroll
    for (int o = 16; o > 0; o >>= 1)
        s += __shfl_xor_sync(0xffffffffu, s, o);
    if (lane == 0) red[wrp] = s;
    __syncthreads();
    s = red[lane & 7];
    #pragma unroll
    for (int o = 4; o > 0; o >>= 1)
        s += __shfl_xor_sync(0xffffffffu, s, o);

    const float inv = 1.f / s;
    #pragma unroll
    for (int i = 0; i < NQ / 256; i++) p[tid + i * 256] = v[i] * inv;
}

// ---------------------------------------------------------------------------
// Column-sum reciprocal over latent axis: rs[b][n] = 1/(1e-9 + sum_k attn)
// ---------------------------------------------------------------------------
__global__ __launch_bounds__(256) void colsum_kernel(
    const float* __restrict__ attn, float* __restrict__ rs)
{
    const int idx = blockIdx.x * blockDim.x + threadIdx.x;
    if (idx >= BQ * NQ) return;
    const int b = idx / NQ, n = idx % NQ;
    const float* p = attn + (size_t)b * KQ * NQ + n;
    float s = 0.f;
    #pragma unroll
    for (int k = 0; k < KQ; k++) s += p[(size_t)k * NQ];
    rs[idx] = 1.f / (1e-9f + s);
}

// ---------------------------------------------------------------------------
// Fused lin1 + renorm-scale + rank + bf16 convert. (R9 per-block config)
// GRID ORDER: blockIdx.x = m (16, fastest) so blocks sharing an attn B-slab
// are schedule-adjacent -> attn served from L2 instead of 16x DRAM re-read.
// ---------------------------------------------------------------------------
__global__ __launch_bounds__(256) void lin1_rank_kernel(
    const float* __restrict__ l1T,    // [64][512] fp32 (k, c)
    const float* __restrict__ attn,   // [b][64][4096] (softmaxed, NOT renormed)
    const float* __restrict__ rs,     // [b][4096] reciprocal colsums
    __nv_bfloat16* __restrict__ y2h)  // [b][512][4096] bf16 out
{
    constexpr int BM = 32, BN = 512, BK = 8;
    constexpr int NT = KQ / BK;       // 8
    __shared__ float As[2][BK][BM];
    __shared__ float Bs[2][BK][BN];

    const int b   = blockIdx.z;
    const int bm0 = blockIdx.x * BM;   // m fastest (L2 reuse of attn slab)
    const int bn0 = blockIdx.y * BN;
    const float* Bp = attn + (size_t)b * KQ * NQ;

    const int tid  = threadIdx.x;
    const int w    = tid / 32;   // warp -> 4 channels
    const int lane = tid % 32;

    float acc[4][16];
    #pragma unroll
    for (int i = 0; i < 4; i++)
        #pragma unroll
        for (int j = 0; j < 16; j++) acc[i][j] = 0.f;

    auto load_tile = [&](int k0, int s) {
        if (tid < 64) {
            int k = tid >> 3, m4 = (tid & 7) << 2;
            cpa16(&As[s][k][m4], &l1T[(size_t)(k0 + k) * CQ + bm0 + m4]);
        }
        #pragma unroll
        for (int r = 0; r < 4; r++) {
            int c = tid + r * 256;
            int k = c >> 7, p = (c & 127) << 2;
            cpa16(&Bs[s][k][p], &Bp[(size_t)(k0 + k) * NQ + bn0 + p]);
        }
        cpa_commit();
    };

    load_tile(0, 0);
    for (int t = 0; t < NT; t++) {
        cpa_wait<0>();
        __syncthreads();
        if (t + 1 < NT) load_tile((t + 1) * BK, (t + 1) & 1);
        const int s = t & 1;

        #pragma unroll
        for (int k = 0; k < BK; k++) {
            float4 av = *reinterpret_cast<const float4*>(&As[s][k][w * 4]);
            float a_[4] = {av.x, av.y, av.z, av.w};
            float bv[16];
            #pragma unroll
            for (int g = 0; g < 4; g++)
                *reinterpret_cast<float4*>(&bv[g * 4]) =
                    *reinterpret_cast<const float4*>(&Bs[s][k][g * 128 + lane * 4]);
            #pragma unroll
            for (int i = 0; i < 4; i++)
                #pragma unroll
                for (int j = 0; j < 16; j++)
                    acc[i][j] += a_[i] * bv[j];
        }
    }

    // renorm scale: acc[i][j] *= rs[b][n]
    {
        const float* rp = rs + (size_t)b * NQ + bn0;
        #pragma unroll
        for (int g = 0; g < 4; g++) {
            float4 rv = *reinterpret_cast<const float4*>(&rp[g * 128 + lane * 4]);
            float rr[4] = {rv.x, rv.y, rv.z, rv.w};
            #pragma unroll
            for (int i = 0; i < 4; i++)
                #pragma unroll
                for (int uu = 0; uu < 4; uu++)
                    acc[i][g * 4 + uu] *= rr[uu];
        }
    }

    // Rank + scale + bf16 per channel row (warp-local, no sync needed)
    #pragma unroll
    for (int i = 0; i < 4; i++) {
        uint32_t u[16];
        #pragma unroll
        for (int j = 0; j < 16; j++) {
            uint32_t bits = __float_as_uint(acc[i][j]);
            u[j] = bits ^ (uint32_t)(((int)bits >> 31) | 0x80000000);
        }
        uint32_t prefix = 0;
        #pragma unroll
        for (int bit = 31; bit >= 0; bit--) {
            uint32_t cand = prefix | (1u << bit);
            int cnt = 0;
            #pragma unroll
            for (int j = 0; j < 16; j++) cnt += (u[j] >= cand);
            cnt = __reduce_add_sync(0xffffffffu, cnt);
            if (cnt >= 256) prefix = cand;
        }
        const uint32_t thr_u = prefix;

        const int m = bm0 + w * 4 + i;
        __nv_bfloat16* q = y2h + (size_t)b * CQ * NQ + (size_t)m * NQ + bn0;
        #pragma unroll
        for (int g = 0; g < 4; g++) {
            float v[4];
            #pragma unroll
            for (int uu = 0; uu < 4; uu++) {
                const int j = g * 4 + uu;
                v[uu] = (u[j] < thr_u) ? 0.75f * acc[i][j] : 1.25f * acc[i][j];
            }
            __nv_bfloat162 h0 = __float22bfloat162_rn(make_float2(v[0], v[1]));
            __nv_bfloat162 h1 = __float22bfloat162_rn(make_float2(v[2], v[3]));
            uint2 st;
            st.x = *reinterpret_cast<uint32_t*>(&h0);
            st.y = *reinterpret_cast<uint32_t*>(&h1);
            *reinterpret_cast<uint2*>(&q[g * 128 + lane * 4]) = st;
        }
    }
}

// ---------------------------------------------------------------------------
// BF16 tensor-core conv2 (mma.sync; tcgen05 rejected by harness .target
// sm_103). At the HMMA issue ceiling (~136 TF/s): BM=BN=128, warp 64x32,
// S=3, m-fastest grid, cp.async.cg loads, 2 blocks/SM. DO NOT retile.
// Out[b][m][n] = relu( relu( sum_c W2[m][c]*y2[b][c][n] ) + x[b][m][n] )
// ---------------------------------------------------------------------------
__device__ __forceinline__ void mma_bf16(float d[4], const uint32_t a[4],
                                         const uint32_t b0, const uint32_t b1) {
    asm volatile(
        "mma.sync.aligned.m16n8k16.row.col.f32.bf16.bf16.f32 "
        "{%0,%1,%2,%3}, {%4,%5,%6,%7}, {%8,%9}, {%0,%1,%2,%3};"
        : "+f"(d[0]), "+f"(d[1]), "+f"(d[2]), "+f"(d[3])
        : "r"(a[0]), "r"(a[1]), "r"(a[2]), "r"(a[3]), "r"(b0), "r"(b1));
}
__device__ __forceinline__ void ldsm_x4_trans(uint32_t r[4], uint32_t addr) {
    asm volatile(
        "ldmatrix.sync.aligned.m8n8.x4.trans.shared.b16 {%0,%1,%2,%3}, [%4];"
        : "=r"(r[0]), "=r"(r[1]), "=r"(r[2]), "=r"(r[3]) : "r"(addr));
}

__global__ __launch_bounds__(256) void conv2_bf16_kernel(
    const __nv_bfloat16* __restrict__ w2h,  // [c][m] bf16
    const __nv_bfloat16* __restrict__ y2h,  // [b][c][n] bf16
    const float* __restrict__ x,            // residual fp32
    float* __restrict__ Out)
{
    constexpr int BM = 128, BN = 128, BK = 32, S = 3;
    extern __shared__ __align__(16) unsigned char cdyn[];
    typedef __nv_bfloat16 (*TileP)[BK][BM];
    TileP As = reinterpret_cast<TileP>(cdyn);
    TileP Bs = reinterpret_cast<TileP>(cdyn + (size_t)S * BK * BM * sizeof(__nv_bfloat16));

    const int b   = blockIdx.z;
    const int bm0 = blockIdx.x * BM;   // m fastest (L2 reuse of B tile)
    const int bn0 = blockIdx.y * BN;
    const __nv_bfloat16* Bp = y2h + (size_t)b * CQ * NQ;

    const int tid  = threadIdx.x;
    const int wid  = tid / 32;
    const int lane = tid % 32;
    const int wm   = wid % 2;
    const int wn   = wid / 2;
    const int m0w  = wm * 64;
    const int n0w  = wn * 32;
    const int g4   = lane / 4;
    const int t4   = lane % 4;

    float acc[4][4][4];
    #pragma unroll
    for (int i = 0; i < 4; i++)
        #pragma unroll
        for (int j = 0; j < 4; j++)
            #pragma unroll
            for (int u = 0; u < 4; u++) acc[i][j][u] = 0.f;

    auto swz = [](int e, int k) -> int {
        return ((((e >> 3) ^ (k & 7)) << 3) | (e & 7));
    };

    auto load_tile = [&](int k0, int s) {
        #pragma unroll
        for (int i = tid; i < 512; i += 256) {
            int k = i >> 4, cc = i & 15;
            cpa16cg(&As[s][k][(cc ^ (k & 7)) << 3],
                    &w2h[(size_t)(k0 + k) * CQ + bm0 + (cc << 3)]);
        }
        #pragma unroll
        for (int i = tid; i < 512; i += 256) {
            int k = i >> 4, cc = i & 15;
            cpa16cg(&Bs[s][k][(cc ^ (k & 7)) << 3],
                    &Bp[(size_t)(k0 + k) * NQ + bn0 + (cc << 3)]);
        }
        cpa_commit();
    };

    constexpr int NT = CQ / BK;            // 16
    load_tile(0, 0);
    load_tile(BK, 1);

    for (int t = 0; t < NT; t++) {
        if (t < NT - 2) cpa_wait<1>();
        else            cpa_wait<0>();      // drain phase
        __syncthreads();
        if (t + 2 < NT) load_tile((t + 2) * BK, (t + 2) % S);
        const int s = t % S;

        #pragma unroll
        for (int ks = 0; ks < BK; ks += 16) {
            uint32_t a[4][4];
            const int l7  = lane & 7;
            const int kA  = ks + l7 + ((lane >> 4) << 3);
            const int mAo = (lane & 8);
            #pragma unroll
            for (int mt = 0; mt < 4; mt++) {
                const int mbase = m0w + mt * 16 + mAo;
                ldsm_x4_trans(a[mt], smem_u32(&As[s][kA][swz(mbase, kA)]));
            }
            uint32_t bfr[2][4];
            const int kB  = ks + l7 + (lane & 8);
            const int nBo = ((lane >> 4) << 3);
            #pragma unroll
            for (int np = 0; np < 2; np++) {
                const int nbase = n0w + np * 16 + nBo;
                ldsm_x4_trans(bfr[np], smem_u32(&Bs[s][kB][swz(nbase, kB)]));
            }
            #pragma unroll
            for (int mt = 0; mt < 4; mt++)
                #pragma unroll
                for (int nt = 0; nt < 4; nt++) {
                    const uint32_t* bp = bfr[nt >> 1];
                    if ((nt & 1) == 0) mma_bf16(acc[mt][nt], a[mt], bp[0], bp[1]);
                    else               mma_bf16(acc[mt][nt], a[mt], bp[2], bp[3]);
                }
        }
    }

    const float* Xp = x + (size_t)b * CQ * NQ;
    float*       Op = Out + (size_t)b * CQ * NQ;
    #pragma unroll
    for (int mt = 0; mt < 4; mt++) {
        #pragma unroll
        for (int nt = 0; nt < 4; nt++) {
            const int row0 = bm0 + m0w + mt * 16 + g4;
            const int col  = bn0 + n0w + nt * 8 + 2 * t4;
            #pragma unroll
            for (int half = 0; half < 2; half++) {
                const int row = row0 + half * 8;
                float2 r = *reinterpret_cast<const float2*>(&Xp[(size_t)row * NQ + col]);
                float v0 = fmaxf(fmaxf(acc[mt][nt][2*half + 0], 0.f) + r.x, 0.f);
                float v1 = fmaxf(fmaxf(acc[mt][nt][2*half + 1], 0.f) + r.y, 0.f);
                float2 o; o.x = v0; o.y = v1;
                *reinterpret_cast<float2*>(&Op[(size_t)row * NQ + col]) = o;
            }
        }
    }
}

// ---------------------------------------------------------------------------
// Launch
// ---------------------------------------------------------------------------
extern "C" void kernel_launch(void* const* d_in, const int* in_sizes, int n_in,
                              void* d_out, int out_size)
{
    const float* x  = (const float*)d_in[0];
    const float* w1 = (const float*)d_in[1];
    const float* b1 = (const float*)d_in[2];
    const float* l0 = (const float*)d_in[3];
    const float* l1 = (const float*)d_in[4];
    const float* w2 = (const float*)d_in[5];
    float* out = (float*)d_out;

    void *pp_, *ap_, *rs_, *y2h_, *w2h_, *l1t_, *w01_, *b01_;
    cudaGetSymbolAddress(&pp_, g_part);
    cudaGetSymbolAddress(&ap_, g_attn);
    cudaGetSymbolAddress(&rs_, g_rs);
    cudaGetSymbolAddress(&y2h_, g_y2h);
    cudaGetSymbolAddress(&w2h_, g_w2h);
    cudaGetSymbolAddress(&l1t_, g_l1T);
    cudaGetSymbolAddress(&w01_, g_w01T);
    cudaGetSymbolAddress(&b01_, g_b01);
    float*         part  = (float*)pp_;
    float*         attn  = (float*)ap_;
    float*         rs    = (float*)rs_;
    __nv_bfloat16* y2h   = (__nv_bfloat16*)y2h_;
    __nv_bfloat16* w2h   = (__nv_bfloat16*)w2h_;
    float*         l1T   = (float*)l1t_;
    float*         w01T  = (float*)w01_;
    float*         b01   = (float*)b01_;

    // conv2: 3 stages x 32k x (128+128) bf16 = 48KB dynamic smem
    const int conv2_smem = 3 * 32 * (128 + 128) * 2;
    cudaFuncSetAttribute(conv2_bf16_kernel,
                         cudaFuncAttributeMaxDynamicSharedMemorySize, conv2_smem);

    // Weight prep
    transpose_bf16_kernel<<<dim3(CQ/32, CQ/32), dim3(32, 8)>>>(w2, w2h, CQ, CQ);
    transpose_kernel<<<dim3(KQ/32, CQ/32), dim3(32, 8)>>>(l1, l1T, CQ, KQ);
    fuse_w01_kernel<<<dim3(CQ/16, KQ/16), dim3(16, 16)>>>(w1, l0, b1, w01T, b01);

    // Fused conv1+lin0 (fp32, split-K=2): partials of (L0@W1)@x (+bias in half 0)
    gemm_nt_splitk_kernel<KQ, CQ/SPLITK, NQ, 64, 128, 16, 8, 8, 1, 3>
        <<<dim3(NQ / 128, SPLITK, BQ), 128>>>(w01T, x, b01, part, CQ);

    // softmax over tokens (adds the SPLITK partials on load)
    softmax_kernel<<<BQ * KQ, 256>>>(part, attn);
    colsum_kernel<<<(BQ * NQ) / 256, 256>>>(attn, rs);

    // Fused lin1 + renorm + rank + bf16 (m-fastest grid for attn L2 reuse)
    lin1_rank_kernel<<<dim3(CQ / 32, NQ / 512, BQ), 256>>>(l1T, attn, rs, y2h);

    // conv2 via bf16 mma.sync (m-fastest grid) + fused relu/residual/relu
    conv2_bf16_kernel<<<dim3(CQ / 128, NQ / 128, BQ), 256, conv2_smem>>>(
        w2h, y2h, x, out);
}

// round 17
// speedup vs baseline: 1.5359x; 1.5359x over previous
#include <cuda_runtime.h>
#include <cuda_bf16.h>
#include <math.h>
#include <stdint.h>

// Problem dims
#define BQ 16
#define CQ 512
#define NQ 4096   // H*W
#define KQ 64
#define SPLITK 2

// Scratch (allocation-free rule: device globals)
__device__ __align__(128) float         g_part[SPLITK][BQ * KQ * NQ]; // split-k partials
__device__ __align__(128) float         g_attn[BQ * KQ * NQ]; // attn probs (softmaxed)
__device__ __align__(128) float         g_rs  [BQ * NQ];      // 1/(1e-9+colsum)
__device__ __align__(128) __nv_bfloat16 g_y2h [BQ * CQ * NQ]; // ranked y2, bf16 [b][c][n]
__device__ __align__(128) __nv_bfloat16 g_w2h [CQ * CQ];      // conv2 weight [c][o] bf16
__device__ __align__(128) float         g_l1T [KQ * CQ];      // lin1 weight [k][c] fp32
__device__ __align__(128) float         g_w01T[CQ * KQ];      // fused (L0@W1)^T [c][k]
__device__ __align__(128) float         g_b01 [KQ];           // fused bias L0@b1

// ---------------------------------------------------------------------------
// helpers
// ---------------------------------------------------------------------------
__device__ __forceinline__ void cpa16(void* smem_dst, const void* gmem_src) {
    unsigned sa = (unsigned)__cvta_generic_to_shared(smem_dst);
    asm volatile("cp.async.ca.shared.global [%0], [%1], 16;" :: "r"(sa), "l"(gmem_src));
}
__device__ __forceinline__ void cpa16cg(void* smem_dst, const void* gmem_src) {
    unsigned sa = (unsigned)__cvta_generic_to_shared(smem_dst);
    asm volatile("cp.async.cg.shared.global [%0], [%1], 16;" :: "r"(sa), "l"(gmem_src));
}
__device__ __forceinline__ void cpa_commit() {
    asm volatile("cp.async.commit_group;" ::: "memory");
}
template<int N>
__device__ __forceinline__ void cpa_wait() {
    asm volatile("cp.async.wait_group %0;" :: "n"(N) : "memory");
}
__device__ __forceinline__ uint32_t smem_u32(const void* p) {
    return (uint32_t)__cvta_generic_to_shared(p);
}

// ---------------------------------------------------------------------------
// Transpose fp32: AT[k][m] = A[m][k]
// ---------------------------------------------------------------------------
__global__ __launch_bounds__(256) void transpose_kernel(
    const float* __restrict__ A, float* __restrict__ AT, int M, int K)
{
    __shared__ float t[32][33];
    const int m0 = blockIdx.y * 32, k0 = blockIdx.x * 32;
    const int x = threadIdx.x, y = threadIdx.y;
    #pragma unroll
    for (int yy = y; yy < 32; yy += 8)
        t[yy][x] = A[(size_t)(m0 + yy) * K + k0 + x];
    __syncthreads();
    #pragma unroll
    for (int yy = y; yy < 32; yy += 8)
        AT[(size_t)(k0 + yy) * M + m0 + x] = t[x][yy];
}

// Transpose + bf16 convert: AT[k][m] = bf16(A[m][k])
__global__ __launch_bounds__(256) void transpose_bf16_kernel(
    const float* __restrict__ A, __nv_bfloat16* __restrict__ AT, int M, int K)
{
    __shared__ float t[32][33];
    const int m0 = blockIdx.y * 32, k0 = blockIdx.x * 32;
    const int x = threadIdx.x, y = threadIdx.y;
    #pragma unroll
    for (int yy = y; yy < 32; yy += 8)
        t[yy][x] = A[(size_t)(m0 + yy) * K + k0 + x];
    __syncthreads();
    #pragma unroll
    for (int yy = y; yy < 32; yy += 8)
        AT[(size_t)(k0 + yy) * M + m0 + x] = __float2bfloat16_rn(t[x][yy]);
}

// ---------------------------------------------------------------------------
// Weight fusion: W01T[c][k] = sum_o W1[o][c] * L0[k][o], b01[k] = L0@b1
// ---------------------------------------------------------------------------
__global__ __launch_bounds__(256) void fuse_w01_kernel(
    const float* __restrict__ w1, const float* __restrict__ l0,
    const float* __restrict__ b1, float* __restrict__ w01T, float* __restrict__ b01)
{
    __shared__ float sw[16][17];
    __shared__ float sl[16][17];
    const int c0 = blockIdx.x * 16, k0 = blockIdx.y * 16;
    const int tx = threadIdx.x, ty = threadIdx.y;
    float acc = 0.f;
    for (int o0 = 0; o0 < CQ; o0 += 16) {
        sw[ty][tx] = w1[(size_t)(o0 + ty) * CQ + c0 + tx];
        sl[ty][tx] = l0[(size_t)(k0 + ty) * CQ + o0 + tx];
        __syncthreads();
        #pragma unroll
        for (int o = 0; o < 16; o++)
            acc += sw[o][tx] * sl[ty][o];
        __syncthreads();
    }
    w01T[(size_t)(c0 + tx) * KQ + k0 + ty] = acc;
    if (blockIdx.x == 0 && tx == 0) {
        const int k = k0 + ty;
        float s = 0.f;
        for (int o = 0; o < CQ; o++) s += l0[(size_t)k * CQ + o] * b1[o];
        b01[k] = s;
    }
}

// ---------------------------------------------------------------------------
// fp32 SGEMM-NT, split-K over gridDim.y: block y handles k-range
// [y*Kc, (y+1)*Kc) and writes its partial (+bias when y==0, EPI==1) to
// part + y*partStride. S-stage cp.async pipeline, tail-safe waits.
// ---------------------------------------------------------------------------
template<int M, int Kc, int Nn, int BM, int BN, int BK, int TM, int TN, int EPI, int S>
__global__ __launch_bounds__((BM/TM)*(BN/TN))
void gemm_nt_splitk_kernel(const float* __restrict__ AT,   // full K x M
                           const float* __restrict__ Bm,   // full K x Nn per batch
                           const float* __restrict__ bias,
                           float* __restrict__ part,       // [SPLITK][B][M][Nn]
                           int Kfull)
{
    constexpr int THREADS = (BM/TM)*(BN/TN);
    __shared__ float As[S][BK][BM];
    __shared__ float Bs[S][BK][BN];

    const int b    = blockIdx.z;
    const int half = blockIdx.y;
    const int koff = half * Kc;
    const int bm0  = 0;
    const int bn0  = blockIdx.x * BN;
    const float* Bp = Bm + (size_t)b * Kfull * Nn;
    float*       Op = part + (size_t)half * BQ * M * Nn + (size_t)b * M * Nn;

    const int tid = threadIdx.x;
    const int tx  = tid % (BN/TN);
    const int ty  = tid / (BN/TN);

    float acc[TM][TN];
    #pragma unroll
    for (int i = 0; i < TM; i++)
        #pragma unroll
        for (int j = 0; j < TN; j++) acc[i][j] = 0.f;

    auto load_tile = [&](int k0, int s) {
        #pragma unroll
        for (int i = tid; i < BK*BM/4; i += THREADS) {
            int k = (i*4) / BM, m = (i*4) % BM;
            cpa16(&As[s][k][m], &AT[(size_t)(koff + k0 + k) * M + bm0 + m]);
        }
        #pragma unroll
        for (int i = tid; i < BK*BN/4; i += THREADS) {
            int k = (i*4) / BN, n = (i*4) % BN;
            cpa16(&Bs[s][k][n], &Bp[(size_t)(koff + k0 + k) * Nn + bn0 + n]);
        }
        cpa_commit();
    };

    constexpr int NT = Kc / BK;
    #pragma unroll
    for (int p = 0; p < S - 1; p++) load_tile(p * BK, p);

    for (int t = 0; t < NT; t++) {
        if (t < NT - (S - 1)) cpa_wait<S - 2>();
        else                  cpa_wait<0>();
        __syncthreads();
        if (t + S - 1 < NT) load_tile((t + S - 1) * BK, (t + S - 1) % S);

        const int s = t % S;
        float a[2][TM], bb[2][TN];
        #pragma unroll
        for (int v = 0; v < TM; v += 4)
            *reinterpret_cast<float4*>(&a[0][v]) =
                *reinterpret_cast<const float4*>(&As[s][0][ty*TM + v]);
        #pragma unroll
        for (int v = 0; v < TN; v += 4)
            *reinterpret_cast<float4*>(&bb[0][v]) =
                *reinterpret_cast<const float4*>(&Bs[s][0][tx*TN + v]);

        #pragma unroll
        for (int k = 0; k < BK; k++) {
            if (k + 1 < BK) {
                #pragma unroll
                for (int v = 0; v < TM; v += 4)
                    *reinterpret_cast<float4*>(&a[(k+1)&1][v]) =
                        *reinterpret_cast<const float4*>(&As[s][k+1][ty*TM + v]);
                #pragma unroll
                for (int v = 0; v < TN; v += 4)
                    *reinterpret_cast<float4*>(&bb[(k+1)&1][v]) =
                        *reinterpret_cast<const float4*>(&Bs[s][k+1][tx*TN + v]);
            }
            const int c = k & 1;
            #pragma unroll
            for (int i = 0; i < TM; i++)
                #pragma unroll
                for (int j = 0; j < TN; j++)
                    acc[i][j] += a[c][i] * bb[c][j];
        }
    }

    #pragma unroll
    for (int i = 0; i < TM; i++) {
        const int m = bm0 + ty * TM + i;
        float bval = 0.f;
        if (EPI == 1 && half == 0) bval = bias[m];
        #pragma unroll
        for (int j = 0; j < TN; j += 4) {
            const int n = bn0 + tx * TN + j;
            float vv[4];
            #pragma unroll
            for (int u = 0; u < 4; u++) vv[u] = acc[i][j + u];
            if (EPI == 1 && half == 0) {
                #pragma unroll
                for (int u = 0; u < 4; u++) vv[u] += bval;
            }
            float4 o; o.x = vv[0]; o.y = vv[1]; o.z = vv[2]; o.w = vv[3];
            *reinterpret_cast<float4*>(&Op[(size_t)m * Nn + n]) = o;
        }
    }
}

// ---------------------------------------------------------------------------
// Softmax over token axis — sums the SPLITK partials (ascending half order =
// k-ascending reassociation), then softmax. Warp-shuffle reductions.
// ---------------------------------------------------------------------------
__global__ __launch_bounds__(256) void softmax_kernel(
    const float* __restrict__ part, float* __restrict__ attn)
{
    const int row = blockIdx.x;
    float* p = attn + (size_t)row * NQ;
    const int tid  = threadIdx.x;
    const int lane = tid & 31;
    const int wrp  = tid >> 5;
    __shared__ float red[8];
    const size_t stride = (size_t)BQ * KQ * NQ;

    float v[NQ / 256];
    float m = -INFINITY;
    #pragma unroll
    for (int i = 0; i < NQ / 256; i++) {
        const size_t off = (size_t)row * NQ + tid + i * 256;
        float s0 = part[off];
        #pragma unroll
        for (int h = 1; h < SPLITK; h++) s0 += part[off + h * stride];
        v[i] = s0;
        m = fmaxf(m, v[i]);
    }
    #pragma unroll
    for (int o = 16; o > 0; o >>= 1)
        m = fmaxf(m, __shfl_xor_sync(0xffffffffu, m, o));
    if (lane == 0) red[wrp] = m;
    __syncthreads();
    m = red[lane & 7];
    #pragma unroll
    for (int o = 4; o > 0; o >>= 1)
        m = fmaxf(m, __shfl_xor_sync(0xffffffffu, m, o));

    float s = 0.f;
    #pragma unroll
    for (int i = 0; i < NQ / 256; i++) {
        v[i] = expf(v[i] - m);
        s += v[i];
    }
    #pragma unroll
    for (int o = 16; o > 0; o >>= 1)
        s += __shfl_xor_sync(0xffffffffu, s, o);
    if (lane == 0) red[wrp] = s;
    __syncthreads();
    s = red[lane & 7];
    #pragma unroll
    for (int o = 4; o > 0; o >>= 1)
        s += __shfl_xor_sync(0xffffffffu, s, o);

    const float inv = 1.f / s;
    #pragma unroll
    for (int i = 0; i < NQ / 256; i++) p[tid + i * 256] = v[i] * inv;
}

// ---------------------------------------------------------------------------
// Column-sum reciprocal over latent axis: rs[b][n] = 1/(1e-9 + sum_k attn)
// ---------------------------------------------------------------------------
__global__ __launch_bounds__(256) void colsum_kernel(
    const float* __restrict__ attn, float* __restrict__ rs)
{
    const int idx = blockIdx.x * blockDim.x + threadIdx.x;
    if (idx >= BQ * NQ) return;
    const int b = idx / NQ, n = idx % NQ;
    const float* p = attn + (size_t)b * KQ * NQ + n;
    float s = 0.f;
    #pragma unroll
    for (int k = 0; k < KQ; k++) s += p[(size_t)k * NQ];
    rs[idx] = 1.f / (1e-9f + s);
}

// ---------------------------------------------------------------------------
// Fused lin1 + renorm-scale + rank + bf16 convert. (R9 per-block config)
// GRID ORDER: blockIdx.x = m (16, fastest) so blocks sharing an attn B-slab
// are schedule-adjacent -> attn served from L2 instead of 16x DRAM re-read.
// ---------------------------------------------------------------------------
__global__ __launch_bounds__(256) void lin1_rank_kernel(
    const float* __restrict__ l1T,    // [64][512] fp32 (k, c)
    const float* __restrict__ attn,   // [b][64][4096] (softmaxed, NOT renormed)
    const float* __restrict__ rs,     // [b][4096] reciprocal colsums
    __nv_bfloat16* __restrict__ y2h)  // [b][512][4096] bf16 out
{
    constexpr int BM = 32, BN = 512, BK = 8;
    constexpr int NT = KQ / BK;       // 8
    __shared__ float As[2][BK][BM];
    __shared__ float Bs[2][BK][BN];

    const int b   = blockIdx.z;
    const int bm0 = blockIdx.x * BM;   // m fastest (L2 reuse of attn slab)
    const int bn0 = blockIdx.y * BN;
    const float* Bp = attn + (size_t)b * KQ * NQ;

    const int tid  = threadIdx.x;
    const int w    = tid / 32;   // warp -> 4 channels
    const int lane = tid % 32;

    float acc[4][16];
    #pragma unroll
    for (int i = 0; i < 4; i++)
        #pragma unroll
        for (int j = 0; j < 16; j++) acc[i][j] = 0.f;

    auto load_tile = [&](int k0, int s) {
        if (tid < 64) {
            int k = tid >> 3, m4 = (tid & 7) << 2;
            cpa16(&As[s][k][m4], &l1T[(size_t)(k0 + k) * CQ + bm0 + m4]);
        }
        #pragma unroll
        for (int r = 0; r < 4; r++) {
            int c = tid + r * 256;
            int k = c >> 7, p = (c & 127) << 2;
            cpa16(&Bs[s][k][p], &Bp[(size_t)(k0 + k) * NQ + bn0 + p]);
        }
        cpa_commit();
    };

    load_tile(0, 0);
    for (int t = 0; t < NT; t++) {
        cpa_wait<0>();
        __syncthreads();
        if (t + 1 < NT) load_tile((t + 1) * BK, (t + 1) & 1);
        const int s = t & 1;

        #pragma unroll
        for (int k = 0; k < BK; k++) {
            float4 av = *reinterpret_cast<const float4*>(&As[s][k][w * 4]);
            float a_[4] = {av.x, av.y, av.z, av.w};
            float bv[16];
            #pragma unroll
            for (int g = 0; g < 4; g++)
                *reinterpret_cast<float4*>(&bv[g * 4]) =
                    *reinterpret_cast<const float4*>(&Bs[s][k][g * 128 + lane * 4]);
            #pragma unroll
            for (int i = 0; i < 4; i++)
                #pragma unroll
                for (int j = 0; j < 16; j++)
                    acc[i][j] += a_[i] * bv[j];
        }
    }

    // renorm scale: acc[i][j] *= rs[b][n]
    {
        const float* rp = rs + (size_t)b * NQ + bn0;
        #pragma unroll
        for (int g = 0; g < 4; g++) {
            float4 rv = *reinterpret_cast<const float4*>(&rp[g * 128 + lane * 4]);
            float rr[4] = {rv.x, rv.y, rv.z, rv.w};
            #pragma unroll
            for (int i = 0; i < 4; i++)
                #pragma unroll
                for (int uu = 0; uu < 4; uu++)
                    acc[i][g * 4 + uu] *= rr[uu];
        }
    }

    // Rank + scale + bf16 per channel row (warp-local, no sync needed)
    #pragma unroll
    for (int i = 0; i < 4; i++) {
        uint32_t u[16];
        #pragma unroll
        for (int j = 0; j < 16; j++) {
            uint32_t bits = __float_as_uint(acc[i][j]);
            u[j] = bits ^ (uint32_t)(((int)bits >> 31) | 0x80000000);
        }
        uint32_t prefix = 0;
        #pragma unroll
        for (int bit = 31; bit >= 0; bit--) {
            uint32_t cand = prefix | (1u << bit);
            int cnt = 0;
            #pragma unroll
            for (int j = 0; j < 16; j++) cnt += (u[j] >= cand);
            cnt = __reduce_add_sync(0xffffffffu, cnt);
            if (cnt >= 256) prefix = cand;
        }
        const uint32_t thr_u = prefix;

        const int m = bm0 + w * 4 + i;
        __nv_bfloat16* q = y2h + (size_t)b * CQ * NQ + (size_t)m * NQ + bn0;
        #pragma unroll
        for (int g = 0; g < 4; g++) {
            float v[4];
            #pragma unroll
            for (int uu = 0; uu < 4; uu++) {
                const int j = g * 4 + uu;
                v[uu] = (u[j] < thr_u) ? 0.75f * acc[i][j] : 1.25f * acc[i][j];
            }
            __nv_bfloat162 h0 = __float22bfloat162_rn(make_float2(v[0], v[1]));
            __nv_bfloat162 h1 = __float22bfloat162_rn(make_float2(v[2], v[3]));
            uint2 st;
            st.x = *reinterpret_cast<uint32_t*>(&h0);
            st.y = *reinterpret_cast<uint32_t*>(&h1);
            *reinterpret_cast<uint2*>(&q[g * 128 + lane * 4]) = st;
        }
    }
}

// ---------------------------------------------------------------------------
// BF16 tensor-core conv2 (mma.sync; tcgen05 rejected by harness .target
// sm_103). At the HMMA issue ceiling (~136 TF/s): BM=BN=128, warp 64x32,
// S=3, m-fastest grid, cp.async.cg loads, 2 blocks/SM. DO NOT retile.
// Out[b][m][n] = relu( relu( sum_c W2[m][c]*y2[b][c][n] ) + x[b][m][n] )
// ---------------------------------------------------------------------------
__device__ __forceinline__ void mma_bf16(float d[4], const uint32_t a[4],
                                         const uint32_t b0, const uint32_t b1) {
    asm volatile(
        "mma.sync.aligned.m16n8k16.row.col.f32.bf16.bf16.f32 "
        "{%0,%1,%2,%3}, {%4,%5,%6,%7}, {%8,%9}, {%0,%1,%2,%3};"
        : "+f"(d[0]), "+f"(d[1]), "+f"(d[2]), "+f"(d[3])
        : "r"(a[0]), "r"(a[1]), "r"(a[2]), "r"(a[3]), "r"(b0), "r"(b1));
}
__device__ __forceinline__ void ldsm_x4_trans(uint32_t r[4], uint32_t addr) {
    asm volatile(
        "ldmatrix.sync.aligned.m8n8.x4.trans.shared.b16 {%0,%1,%2,%3}, [%4];"
        : "=r"(r[0]), "=r"(r[1]), "=r"(r[2]), "=r"(r[3]) : "r"(addr));
}

__global__ __launch_bounds__(256) void conv2_bf16_kernel(
    const __nv_bfloat16* __restrict__ w2h,  // [c][m] bf16
    const __nv_bfloat16* __restrict__ y2h,  // [b][c][n] bf16
    const float* __restrict__ x,            // residual fp32
    float* __restrict__ Out)
{
    constexpr int BM = 128, BN = 128, BK = 32, S = 3;
    extern __shared__ __align__(16) unsigned char cdyn[];
    typedef __nv_bfloat16 (*TileP)[BK][BM];
    TileP As = reinterpret_cast<TileP>(cdyn);
    TileP Bs = reinterpret_cast<TileP>(cdyn + (size_t)S * BK * BM * sizeof(__nv_bfloat16));

    const int b   = blockIdx.z;
    const int bm0 = blockIdx.x * BM;   // m fastest (L2 reuse of B tile)
    const int bn0 = blockIdx.y * BN;
    const __nv_bfloat16* Bp = y2h + (size_t)b * CQ * NQ;

    const int tid  = threadIdx.x;
    const int wid  = tid / 32;
    const int lane = tid % 32;
    const int wm   = wid % 2;
    const int wn   = wid / 2;
    const int m0w  = wm * 64;
    const int n0w  = wn * 32;
    const int g4   = lane / 4;
    const int t4   = lane % 4;

    float acc[4][4][4];
    #pragma unroll
    for (int i = 0; i < 4; i++)
        #pragma unroll
        for (int j = 0; j < 4; j++)
            #pragma unroll
            for (int u = 0; u < 4; u++) acc[i][j][u] = 0.f;

    auto swz = [](int e, int k) -> int {
        return ((((e >> 3) ^ (k & 7)) << 3) | (e & 7));
    };

    auto load_tile = [&](int k0, int s) {
        #pragma unroll
        for (int i = tid; i < 512; i += 256) {
            int k = i >> 4, cc = i & 15;
            cpa16cg(&As[s][k][(cc ^ (k & 7)) << 3],
                    &w2h[(size_t)(k0 + k) * CQ + bm0 + (cc << 3)]);
        }
        #pragma unroll
        for (int i = tid; i < 512; i += 256) {
            int k = i >> 4, cc = i & 15;
            cpa16cg(&Bs[s][k][(cc ^ (k & 7)) << 3],
                    &Bp[(size_t)(k0 + k) * NQ + bn0 + (cc << 3)]);
        }
        cpa_commit();
    };

    constexpr int NT = CQ / BK;            // 16
    load_tile(0, 0);
    load_tile(BK, 1);

    for (int t = 0; t < NT; t++) {
        if (t < NT - 2) cpa_wait<1>();
        else            cpa_wait<0>();      // drain phase
        __syncthreads();
        if (t + 2 < NT) load_tile((t + 2) * BK, (t + 2) % S);
        const int s = t % S;

        #pragma unroll
        for (int ks = 0; ks < BK; ks += 16) {
            uint32_t a[4][4];
            const int l7  = lane & 7;
            const int kA  = ks + l7 + ((lane >> 4) << 3);
            const int mAo = (lane & 8);
            #pragma unroll
            for (int mt = 0; mt < 4; mt++) {
                const int mbase = m0w + mt * 16 + mAo;
                ldsm_x4_trans(a[mt], smem_u32(&As[s][kA][swz(mbase, kA)]));
            }
            uint32_t bfr[2][4];
            const int kB  = ks + l7 + (lane & 8);
            const int nBo = ((lane >> 4) << 3);
            #pragma unroll
            for (int np = 0; np < 2; np++) {
                const int nbase = n0w + np * 16 + nBo;
                ldsm_x4_trans(bfr[np], smem_u32(&Bs[s][kB][swz(nbase, kB)]));
            }
            #pragma unroll
            for (int mt = 0; mt < 4; mt++)
                #pragma unroll
                for (int nt = 0; nt < 4; nt++) {
                    const uint32_t* bp = bfr[nt >> 1];
                    if ((nt & 1) == 0) mma_bf16(acc[mt][nt], a[mt], bp[0], bp[1]);
                    else               mma_bf16(acc[mt][nt], a[mt], bp[2], bp[3]);
                }
        }
    }

    const float* Xp = x + (size_t)b * CQ * NQ;
    float*       Op = Out + (size_t)b * CQ * NQ;
    #pragma unroll
    for (int mt = 0; mt < 4; mt++) {
        #pragma unroll
        for (int nt = 0; nt < 4; nt++) {
            const int row0 = bm0 + m0w + mt * 16 + g4;
            const int col  = bn0 + n0w + nt * 8 + 2 * t4;
            #pragma unroll
            for (int half = 0; half < 2; half++) {
                const int row = row0 + half * 8;
                float2 r = *reinterpret_cast<const float2*>(&Xp[(size_t)row * NQ + col]);
                float v0 = fmaxf(fmaxf(acc[mt][nt][2*half + 0], 0.f) + r.x, 0.f);
                float v1 = fmaxf(fmaxf(acc[mt][nt][2*half + 1], 0.f) + r.y, 0.f);
                float2 o; o.x = v0; o.y = v1;
                *reinterpret_cast<float2*>(&Op[(size_t)row * NQ + col]) = o;
            }
        }
    }
}

// ---------------------------------------------------------------------------
// Launch
// ---------------------------------------------------------------------------
extern "C" void kernel_launch(void* const* d_in, const int* in_sizes, int n_in,
                              void* d_out, int out_size)
{
    const float* x  = (const float*)d_in[0];
    const float* w1 = (const float*)d_in[1];
    const float* b1 = (const float*)d_in[2];
    const float* l0 = (const float*)d_in[3];
    const float* l1 = (const float*)d_in[4];
    const float* w2 = (const float*)d_in[5];
    float* out = (float*)d_out;

    void *pp_, *ap_, *rs_, *y2h_, *w2h_, *l1t_, *w01_, *b01_;
    cudaGetSymbolAddress(&pp_, g_part);
    cudaGetSymbolAddress(&ap_, g_attn);
    cudaGetSymbolAddress(&rs_, g_rs);
    cudaGetSymbolAddress(&y2h_, g_y2h);
    cudaGetSymbolAddress(&w2h_, g_w2h);
    cudaGetSymbolAddress(&l1t_, g_l1T);
    cudaGetSymbolAddress(&w01_, g_w01T);
    cudaGetSymbolAddress(&b01_, g_b01);
    float*         part  = (float*)pp_;
    float*         attn  = (float*)ap_;
    float*         rs    = (float*)rs_;
    __nv_bfloat16* y2h   = (__nv_bfloat16*)y2h_;
    __nv_bfloat16* w2h   = (__nv_bfloat16*)w2h_;
    float*         l1T   = (float*)l1t_;
    float*         w01T  = (float*)w01_;
    float*         b01   = (float*)b01_;

    // conv2: 3 stages x 32k x (128+128) bf16 = 48KB dynamic smem
    const int conv2_smem = 3 * 32 * (128 + 128) * 2;
    cudaFuncSetAttribute(conv2_bf16_kernel,
                         cudaFuncAttributeMaxDynamicSharedMemorySize, conv2_smem);

    // Weight prep
    transpose_bf16_kernel<<<dim3(CQ/32, CQ/32), dim3(32, 8)>>>(w2, w2h, CQ, CQ);
    transpose_kernel<<<dim3(KQ/32, CQ/32), dim3(32, 8)>>>(l1, l1T, CQ, KQ);
    fuse_w01_kernel<<<dim3(CQ/16, KQ/16), dim3(16, 16)>>>(w1, l0, b1, w01T, b01);

    // Fused conv1+lin0 (fp32, split-K=2): partials of (L0@W1)@x (+bias in half 0)
    gemm_nt_splitk_kernel<KQ, CQ/SPLITK, NQ, 64, 128, 16, 8, 8, 1, 3>
        <<<dim3(NQ / 128, SPLITK, BQ), 128>>>(w01T, x, b01, part, CQ);

    // softmax over tokens (adds the SPLITK partials on load)
    softmax_kernel<<<BQ * KQ, 256>>>(part, attn);
    colsum_kernel<<<(BQ * NQ) / 256, 256>>>(attn, rs);

    // Fused lin1 + renorm + rank + bf16 (m-fastest grid for attn L2 reuse)
    lin1_rank_kernel<<<dim3(CQ / 32, NQ / 512, BQ), 256>>>(l1T, attn, rs, y2h);

    // conv2 via bf16 mma.sync (m-fastest grid) + fused relu/residual/relu
    conv2_bf16_kernel<<<dim3(CQ / 128, NQ / 128, BQ), 256, conv2_smem>>>(
        w2h, y2h, x, out);
}